// round 13
// baseline (speedup 1.0000x reference)
#include <cuda_runtime.h>

// 2-layer GCN, N=100000 nodes, E=1200000 edges, D=64.
//   per layer: xw = X@W ; agg[n] = sum_{e: dst[e]==n} xw[src[e]] ;
//              h = relu(agg + b) + relu(X@Wr + br)
//
// Strategy this round:
//   * CSR built on-device each replay (zero/hist/scan/fill) -> aggregation is
//     an atomic-free warp-per-node gather-reduce (halves L2 traffic vs red.v4).
//   * GEMM inner loop uses packed fma.rn.f32x2 (FFMA2): the swizzled XsT tile
//     already holds row pairs adjacently, so ulonglong2 LDS.128 loads give
//     pre-packed operands for free.

static constexpr int NN = 100000;
static constexpr int EE = 1200000;

// ---- scratch (device globals; allocation-free) ----
__device__ __align__(16) float g_xw [NN * 64];
__device__ __align__(16) float g_agg[NN * 64];
__device__ __align__(16) float g_h1 [NN * 64];
__device__ int g_deg   [NN];
__device__ int g_rowptr[NN + 1];
__device__ int g_cursor[NN];
__device__ int g_col   [EE];

// ============================ CSR build ============================

__global__ __launch_bounds__(256) void zero_deg_k() {
    int i = blockIdx.x * 256 + threadIdx.x;
    if (i < NN) g_deg[i] = 0;
}

__global__ __launch_bounds__(256) void hist_k(const int* __restrict__ dst) {
    int e = blockIdx.x * 256 + threadIdx.x;
    if (e < EE) atomicAdd(&g_deg[dst[e]], 1);
}

// Single-block exclusive scan over g_deg -> g_rowptr (and g_cursor copy).
__global__ __launch_bounds__(1024) void scan_k() {
    __shared__ int ss[1024];
    const int CH = (NN + 1023) / 1024;     // 98 elements per thread
    int t = threadIdx.x;
    int base = t * CH;

    int sum = 0;
    for (int i = 0; i < CH; ++i) {
        int idx = base + i;
        if (idx < NN) sum += g_deg[idx];
    }
    ss[t] = sum;
    __syncthreads();
    // Hillis-Steele inclusive scan
    for (int off = 1; off < 1024; off <<= 1) {
        int v = (t >= off) ? ss[t - off] : 0;
        __syncthreads();
        ss[t] += v;
        __syncthreads();
    }
    int run = ss[t] - sum;                 // exclusive prefix
    for (int i = 0; i < CH; ++i) {
        int idx = base + i;
        if (idx < NN) {
            g_rowptr[idx] = run;
            g_cursor[idx] = run;
            run += g_deg[idx];
        }
    }
    if (t == 1023) g_rowptr[NN] = EE;
}

__global__ __launch_bounds__(256) void fill_k(const int* __restrict__ src,
                                              const int* __restrict__ dst) {
    int e = blockIdx.x * 256 + threadIdx.x;
    if (e < EE) {
        int p = atomicAdd(&g_cursor[dst[e]], 1);
        g_col[p] = src[e];
    }
}

// ===================== aggregation (gather-reduce) =====================
// One warp per node; lane owns a float2 column slice. col[e] load is a
// warp-broadcast; xw gather is a coalesced 256B line pair per iteration.
__global__ __launch_bounds__(256) void agg_k() {
    int wid  = (blockIdx.x * 256 + threadIdx.x) >> 5;
    int lane = threadIdx.x & 31;
    if (wid >= NN) return;

    int beg = g_rowptr[wid];
    int end = g_rowptr[wid + 1];

    const float2* __restrict__ xw2 = (const float2*)g_xw;
    float2 acc = make_float2(0.f, 0.f);

    int e = beg;
    int c = (e < end) ? __ldg(g_col + e) : 0;
    for (; e < end; ++e) {
        int cn = (e + 1 < end) ? __ldg(g_col + e + 1) : 0;   // prefetch next col
        float2 v = __ldg(xw2 + (size_t)c * 32 + lane);
        acc.x += v.x;
        acc.y += v.y;
        c = cn;
    }
    ((float2*)g_agg)[(size_t)wid * 32 + lane] = acc;
}

// ============================== GEMM ==============================

__device__ __forceinline__ unsigned long long fma2(unsigned long long a,
                                                   unsigned long long b,
                                                   unsigned long long c) {
    unsigned long long d;
    asm("fma.rn.f32x2 %0, %1, %2, %3;" : "=l"(d) : "l"(a), "l"(b), "l"(c));
    return d;
}

// swizzled transposed X tile index: element (k, r) of XsT[64][64]
__device__ __forceinline__ int swidx(int k, int r) {
    return (k << 6) + (((((r >> 2) ^ ((k >> 2) & 15))) << 2) | (r & 3));
}

// MODE 0: g_xw = X @ W
// MODE 1: Y = relu(X @ W + bias_r) + relu(g_agg + bias_a)
// XH1: X comes from g_h1. YH1: Y goes to g_h1.
template<int MODE, bool XH1, bool YH1>
__global__ __launch_bounds__(256)
void gemm64_k(const float* __restrict__ Xp,
              const float* __restrict__ W,
              const float* __restrict__ bias_r,
              const float* __restrict__ bias_a,
              float* __restrict__ Yp,
              int n)
{
    __shared__ __align__(16) float XsT[64 * 64];   // transposed + swizzled
    __shared__ __align__(16) float Ws [64 * 64];   // row-major Ws[k*64+j]

    const float* X = XH1 ? (const float*)g_h1 : Xp;
    float*       Y = YH1 ? (float*)g_h1       : Yp;

    const int tid  = threadIdx.x;
    const int row0 = blockIdx.x << 6;

    // Stage W
    const float4* W4 = (const float4*)W;
    float4* Ws4 = (float4*)Ws;
#pragma unroll
    for (int i = 0; i < 4; ++i) Ws4[tid + i * 256] = W4[tid + i * 256];

    // Stage X tile transposed+swizzled
    const float4* X4 = (const float4*)X;
#pragma unroll
    for (int i = 0; i < 4; ++i) {
        int idx = tid + i * 256;
        int r   = idx >> 4;
        int c4  = idx & 15;
        int row = row0 + r;
        float4 v = make_float4(0.f, 0.f, 0.f, 0.f);
        if (row < n) v = X4[row * 16 + c4];
        int c = c4 << 2;
        XsT[swidx(c + 0, r)] = v.x;
        XsT[swidx(c + 1, r)] = v.y;
        XsT[swidx(c + 2, r)] = v.z;
        XsT[swidx(c + 3, r)] = v.w;
    }
    __syncthreads();

    const int j  = tid & 63;   // output column
    const int rg = tid >> 6;   // row group (16 rows)

    unsigned long long acc2[8];
#pragma unroll
    for (int p = 0; p < 8; ++p) acc2[p] = 0ull;

#pragma unroll 8
    for (int k = 0; k < 64; ++k) {
        float wv = Ws[(k << 6) + j];
        unsigned long long wv2;
        asm("mov.b64 %0, {%1, %1};" : "=l"(wv2) : "f"(wv));

        const ulonglong2* xk = (const ulonglong2*)(XsT + (k << 6));
        int sw = (k >> 2) & 15;
        ulonglong2 a0 = xk[((rg << 2) + 0) ^ sw];   // rows +0..3  (2 packed pairs)
        ulonglong2 a1 = xk[((rg << 2) + 1) ^ sw];   // rows +4..7
        ulonglong2 a2 = xk[((rg << 2) + 2) ^ sw];   // rows +8..11
        ulonglong2 a3 = xk[((rg << 2) + 3) ^ sw];   // rows +12..15

        acc2[0] = fma2(a0.x, wv2, acc2[0]);
        acc2[1] = fma2(a0.y, wv2, acc2[1]);
        acc2[2] = fma2(a1.x, wv2, acc2[2]);
        acc2[3] = fma2(a1.y, wv2, acc2[3]);
        acc2[4] = fma2(a2.x, wv2, acc2[4]);
        acc2[5] = fma2(a2.y, wv2, acc2[5]);
        acc2[6] = fma2(a3.x, wv2, acc2[6]);
        acc2[7] = fma2(a3.y, wv2, acc2[7]);
    }

    const int rbase = row0 + (rg << 4);
    if (MODE == 0) {
#pragma unroll
        for (int p = 0; p < 8; ++p) {
            float lo, hi;
            asm("mov.b64 {%0, %1}, %2;" : "=f"(lo), "=f"(hi) : "l"(acc2[p]));
            int r0 = rbase + 2 * p;
            if (r0     < n) g_xw[(size_t)r0 * 64 + j]       = lo;
            if (r0 + 1 < n) g_xw[(size_t)(r0 + 1) * 64 + j] = hi;
        }
    } else {
        float brj = bias_r[j];
        float baj = bias_a[j];
#pragma unroll
        for (int p = 0; p < 8; ++p) {
            float lo, hi;
            asm("mov.b64 {%0, %1}, %2;" : "=f"(lo), "=f"(hi) : "l"(acc2[p]));
            int r0 = rbase + 2 * p;
            if (r0 < n) {
                float conv = g_agg[(size_t)r0 * 64 + j] + baj;
                conv = conv > 0.f ? conv : 0.f;
                float res = lo + brj;
                res = res > 0.f ? res : 0.f;
                Y[(size_t)r0 * 64 + j] = conv + res;
            }
            if (r0 + 1 < n) {
                float conv = g_agg[(size_t)(r0 + 1) * 64 + j] + baj;
                conv = conv > 0.f ? conv : 0.f;
                float res = hi + brj;
                res = res > 0.f ? res : 0.f;
                Y[(size_t)(r0 + 1) * 64 + j] = conv + res;
            }
        }
    }
}

// ============================== launch ==============================

extern "C" void kernel_launch(void* const* d_in, const int* in_sizes, int n_in,
                              void* d_out, int out_size)
{
    const float* feats = (const float*)d_in[0];
    const float* W1    = (const float*)d_in[1];
    const float* b1    = (const float*)d_in[2];
    const float* Wr1   = (const float*)d_in[3];
    const float* br1   = (const float*)d_in[4];
    const float* W2    = (const float*)d_in[5];
    const float* b2    = (const float*)d_in[6];
    const float* Wr2   = (const float*)d_in[7];
    const float* br2   = (const float*)d_in[8];
    const int*   src   = (const int*)d_in[9];
    const int*   dst   = (const int*)d_in[10];
    float*       out   = (float*)d_out;

    const int GB = (NN + 63) >> 6;                 // 1563 gemm blocks
    const int NB = (NN + 255) / 256;               // 391
    const int EB = (EE + 255) / 256;               // 4688
    const int AB = (NN * 32 + 255) / 256;          // 12500 (warp per node)

    // ---- CSR build (per replay, reused by both layers) ----
    zero_deg_k<<<NB, 256>>>();
    hist_k<<<EB, 256>>>(dst);
    scan_k<<<1, 1024>>>();
    fill_k<<<EB, 256>>>(src, dst);

    // ---- Layer 1 ----
    gemm64_k<0, false, false><<<GB, 256>>>(feats, W1, nullptr, nullptr, nullptr, NN);
    agg_k<<<AB, 256>>>();
    gemm64_k<1, false, true ><<<GB, 256>>>(feats, Wr1, br1, b1, nullptr, NN);

    // ---- Layer 2 ----
    gemm64_k<0, true,  false><<<GB, 256>>>(nullptr, W2, nullptr, nullptr, nullptr, NN);
    agg_k<<<AB, 256>>>();
    gemm64_k<1, true,  false><<<GB, 256>>>(nullptr, Wr2, br2, b2, out, NN);
}

// round 14
// speedup vs baseline: 1.3577x; 1.3577x over previous
#include <cuda_runtime.h>

// 2-layer GCN, N=100000 nodes, E=1200000 edges, D=64.
//   per layer: xw = X@W ; agg = segment_sum(xw[src] -> dst) ;
//              h = relu(agg + b) + relu(X@Wr + br)
//
// R13: revert to R11 atomic-scatter plan (CSR build per replay was a net
// loss), keep the packed fma.rn.f32x2 GEMM inner loop from R12.
//
// Launch plan (default stream, graph-capturable, allocation-free):
//   L1: gemm<MODE0>(feats,W1)  -> g_xw, zero g_agg
//       scatter(src,dst)       -> g_agg += g_xw[src]  (red.global.add.v4.f32)
//       gemm<MODE1>(feats,Wr1) -> g_h1 = relu(g_agg+b1) + relu(feats@Wr1+br1)
//   L2: same with g_h1 as input, output to d_out.

static constexpr int NN = 100000;
static constexpr int EE = 1200000;

// Scratch (device globals; allocation-free). 16B-aligned for float4/red.v4.
__device__ __align__(16) float g_xw [NN * 64];
__device__ __align__(16) float g_agg[NN * 64];
__device__ __align__(16) float g_h1 [NN * 64];

// ============================== GEMM ==============================

__device__ __forceinline__ unsigned long long fma2(unsigned long long a,
                                                   unsigned long long b,
                                                   unsigned long long c) {
    unsigned long long d;
    asm("fma.rn.f32x2 %0, %1, %2, %3;" : "=l"(d) : "l"(a), "l"(b), "l"(c));
    return d;
}

// XOR-swizzled transposed X tile index: element (k, r) of XsT[64][64] at
//   k*64 + (((r>>2) ^ ((k>>2)&15)) * 4 + (r&3))
// -> transpose stores ~2-way conflicted, compute reads are broadcast LDS.128.
__device__ __forceinline__ int swidx(int k, int r) {
    return (k << 6) + (((((r >> 2) ^ ((k >> 2) & 15))) << 2) | (r & 3));
}

// MODE 0: g_xw = X @ W ; also zero g_agg rows (scatter accumulates into it).
// MODE 1: Y = relu(X @ W + bias_r) + relu(g_agg + bias_a)
// XH1: X comes from g_h1. YH1: Y goes to g_h1.
template<int MODE, bool XH1, bool YH1>
__global__ __launch_bounds__(256)
void gemm64_k(const float* __restrict__ Xp,
              const float* __restrict__ W,
              const float* __restrict__ bias_r,
              const float* __restrict__ bias_a,
              float* __restrict__ Yp,
              int n)
{
    __shared__ __align__(16) float XsT[64 * 64];   // transposed + swizzled
    __shared__ __align__(16) float Ws [64 * 64];   // row-major Ws[k*64+j]

    const float* X = XH1 ? (const float*)g_h1 : Xp;
    float*       Y = YH1 ? (float*)g_h1       : Yp;

    const int tid  = threadIdx.x;
    const int row0 = blockIdx.x << 6;

    // Stage W (4096 floats = 1024 float4)
    const float4* W4 = (const float4*)W;
    float4* Ws4 = (float4*)Ws;
#pragma unroll
    for (int i = 0; i < 4; ++i) Ws4[tid + i * 256] = W4[tid + i * 256];

    // Stage X tile transposed+swizzled
    const float4* X4 = (const float4*)X;
#pragma unroll
    for (int i = 0; i < 4; ++i) {
        int idx = tid + i * 256;
        int r   = idx >> 4;
        int c4  = idx & 15;
        int row = row0 + r;
        float4 v = make_float4(0.f, 0.f, 0.f, 0.f);
        if (row < n) v = X4[row * 16 + c4];
        int c = c4 << 2;
        XsT[swidx(c + 0, r)] = v.x;
        XsT[swidx(c + 1, r)] = v.y;
        XsT[swidx(c + 2, r)] = v.z;
        XsT[swidx(c + 3, r)] = v.w;
    }
    __syncthreads();

    const int j  = tid & 63;   // output column
    const int rg = tid >> 6;   // row group (16 rows)

    unsigned long long acc2[8];
#pragma unroll
    for (int p = 0; p < 8; ++p) acc2[p] = 0ull;

#pragma unroll 8
    for (int k = 0; k < 64; ++k) {
        float wv = Ws[(k << 6) + j];
        unsigned long long wv2;
        asm("mov.b64 %0, {%1, %1};" : "=l"(wv2) : "f"(wv));

        const ulonglong2* xk = (const ulonglong2*)(XsT + (k << 6));
        int sw = (k >> 2) & 15;
        ulonglong2 a0 = xk[((rg << 2) + 0) ^ sw];   // rows +0..3 (2 packed pairs)
        ulonglong2 a1 = xk[((rg << 2) + 1) ^ sw];   // rows +4..7
        ulonglong2 a2 = xk[((rg << 2) + 2) ^ sw];   // rows +8..11
        ulonglong2 a3 = xk[((rg << 2) + 3) ^ sw];   // rows +12..15

        acc2[0] = fma2(a0.x, wv2, acc2[0]);
        acc2[1] = fma2(a0.y, wv2, acc2[1]);
        acc2[2] = fma2(a1.x, wv2, acc2[2]);
        acc2[3] = fma2(a1.y, wv2, acc2[3]);
        acc2[4] = fma2(a2.x, wv2, acc2[4]);
        acc2[5] = fma2(a2.y, wv2, acc2[5]);
        acc2[6] = fma2(a3.x, wv2, acc2[6]);
        acc2[7] = fma2(a3.y, wv2, acc2[7]);
    }

    const int rbase = row0 + (rg << 4);
    if (MODE == 0) {
#pragma unroll
        for (int p = 0; p < 8; ++p) {
            float lo, hi;
            asm("mov.b64 {%0, %1}, %2;" : "=f"(lo), "=f"(hi) : "l"(acc2[p]));
            int r0 = rbase + 2 * p;
            if (r0 < n) {
                g_xw [(size_t)r0 * 64 + j] = lo;
                g_agg[(size_t)r0 * 64 + j] = 0.f;
            }
            if (r0 + 1 < n) {
                g_xw [(size_t)(r0 + 1) * 64 + j] = hi;
                g_agg[(size_t)(r0 + 1) * 64 + j] = 0.f;
            }
        }
    } else {
        float brj = bias_r[j];
        float baj = bias_a[j];
#pragma unroll
        for (int p = 0; p < 8; ++p) {
            float lo, hi;
            asm("mov.b64 {%0, %1}, %2;" : "=f"(lo), "=f"(hi) : "l"(acc2[p]));
            int r0 = rbase + 2 * p;
            if (r0 < n) {
                float conv = g_agg[(size_t)r0 * 64 + j] + baj;
                conv = conv > 0.f ? conv : 0.f;
                float res = lo + brj;
                res = res > 0.f ? res : 0.f;
                Y[(size_t)r0 * 64 + j] = conv + res;
            }
            if (r0 + 1 < n) {
                float conv = g_agg[(size_t)(r0 + 1) * 64 + j] + baj;
                conv = conv > 0.f ? conv : 0.f;
                float res = hi + brj;
                res = res > 0.f ? res : 0.f;
                Y[(size_t)(r0 + 1) * 64 + j] = conv + res;
            }
        }
    }
}

// ============================ scatter ============================
// Vectorized 16B float atomic add (sm_90+): 4 fp32 adds per L2 atomic op.
__device__ __forceinline__ void red_add_v4(float4* addr, float4 v) {
    asm volatile("red.global.add.v4.f32 [%0], {%1, %2, %3, %4};"
                 :: "l"(addr), "f"(v.x), "f"(v.y), "f"(v.z), "f"(v.w)
                 : "memory");
}

// One thread per (edge, float4-quad): 16 threads per edge, fully coalesced
// 256B gather per edge, 16B vector red per thread.
__global__ __launch_bounds__(256)
void scatter_k(const int* __restrict__ src, const int* __restrict__ dst)
{
    unsigned gid = blockIdx.x * 256u + threadIdx.x;   // EE*16 = 19.2M exact
    unsigned e = gid >> 4;
    unsigned q = gid & 15;
    int s = __ldg(src + e);
    int d = __ldg(dst + e);
    const float4* xw4 = (const float4*)g_xw;
    float4 v = __ldg(xw4 + (size_t)s * 16 + q);
    red_add_v4(((float4*)g_agg) + (size_t)d * 16 + q, v);
}

// ============================== launch ==============================

extern "C" void kernel_launch(void* const* d_in, const int* in_sizes, int n_in,
                              void* d_out, int out_size)
{
    const float* feats = (const float*)d_in[0];
    const float* W1    = (const float*)d_in[1];
    const float* b1    = (const float*)d_in[2];
    const float* Wr1   = (const float*)d_in[3];
    const float* br1   = (const float*)d_in[4];
    const float* W2    = (const float*)d_in[5];
    const float* b2    = (const float*)d_in[6];
    const float* Wr2   = (const float*)d_in[7];
    const float* br2   = (const float*)d_in[8];
    const int*   src   = (const int*)d_in[9];
    const int*   dst   = (const int*)d_in[10];
    float*       out   = (float*)d_out;

    const int GB = (NN + 63) >> 6;            // 1563 blocks
    const int SB = (EE * 16) / 256;           // 75000 blocks

    // ---- Layer 1 ----
    gemm64_k<0, false, false><<<GB, 256>>>(feats, W1, nullptr, nullptr, nullptr, NN);
    scatter_k<<<SB, 256>>>(src, dst);
    gemm64_k<1, false, true ><<<GB, 256>>>(feats, Wr1, br1, b1, nullptr, NN);

    // ---- Layer 2 ----
    gemm64_k<0, true,  false><<<GB, 256>>>(nullptr, W2, nullptr, nullptr, nullptr, NN);
    scatter_k<<<SB, 256>>>(src, dst);
    gemm64_k<1, true,  false><<<GB, 256>>>(nullptr, Wr2, br2, b2, out, NN);
}

// round 15
// speedup vs baseline: 1.3748x; 1.0126x over previous
#include <cuda_runtime.h>

// 2-layer GCN, N=100000 nodes, E=1200000 edges, D=64.
//   per layer: xw = X@W ; agg = segment_sum(xw[src] -> dst) ;
//              h = relu(agg + b) + relu(X@Wr + br)
//
// R13: revert to R11 atomic-scatter plan (CSR build per replay was a net
// loss), keep the packed fma.rn.f32x2 GEMM inner loop from R12.
//
// Launch plan (default stream, graph-capturable, allocation-free):
//   L1: gemm<MODE0>(feats,W1)  -> g_xw, zero g_agg
//       scatter(src,dst)       -> g_agg += g_xw[src]  (red.global.add.v4.f32)
//       gemm<MODE1>(feats,Wr1) -> g_h1 = relu(g_agg+b1) + relu(feats@Wr1+br1)
//   L2: same with g_h1 as input, output to d_out.

static constexpr int NN = 100000;
static constexpr int EE = 1200000;

// Scratch (device globals; allocation-free). 16B-aligned for float4/red.v4.
__device__ __align__(16) float g_xw [NN * 64];
__device__ __align__(16) float g_agg[NN * 64];
__device__ __align__(16) float g_h1 [NN * 64];

// ============================== GEMM ==============================

__device__ __forceinline__ unsigned long long fma2(unsigned long long a,
                                                   unsigned long long b,
                                                   unsigned long long c) {
    unsigned long long d;
    asm("fma.rn.f32x2 %0, %1, %2, %3;" : "=l"(d) : "l"(a), "l"(b), "l"(c));
    return d;
}

// XOR-swizzled transposed X tile index: element (k, r) of XsT[64][64] at
//   k*64 + (((r>>2) ^ ((k>>2)&15)) * 4 + (r&3))
// -> transpose stores ~2-way conflicted, compute reads are broadcast LDS.128.
__device__ __forceinline__ int swidx(int k, int r) {
    return (k << 6) + (((((r >> 2) ^ ((k >> 2) & 15))) << 2) | (r & 3));
}

// MODE 0: g_xw = X @ W ; also zero g_agg rows (scatter accumulates into it).
// MODE 1: Y = relu(X @ W + bias_r) + relu(g_agg + bias_a)
// XH1: X comes from g_h1. YH1: Y goes to g_h1.
template<int MODE, bool XH1, bool YH1>
__global__ __launch_bounds__(256)
void gemm64_k(const float* __restrict__ Xp,
              const float* __restrict__ W,
              const float* __restrict__ bias_r,
              const float* __restrict__ bias_a,
              float* __restrict__ Yp,
              int n)
{
    __shared__ __align__(16) float XsT[64 * 64];   // transposed + swizzled
    __shared__ __align__(16) float Ws [64 * 64];   // row-major Ws[k*64+j]

    const float* X = XH1 ? (const float*)g_h1 : Xp;
    float*       Y = YH1 ? (float*)g_h1       : Yp;

    const int tid  = threadIdx.x;
    const int row0 = blockIdx.x << 6;

    // Stage W (4096 floats = 1024 float4)
    const float4* W4 = (const float4*)W;
    float4* Ws4 = (float4*)Ws;
#pragma unroll
    for (int i = 0; i < 4; ++i) Ws4[tid + i * 256] = W4[tid + i * 256];

    // Stage X tile transposed+swizzled
    const float4* X4 = (const float4*)X;
#pragma unroll
    for (int i = 0; i < 4; ++i) {
        int idx = tid + i * 256;
        int r   = idx >> 4;
        int c4  = idx & 15;
        int row = row0 + r;
        float4 v = make_float4(0.f, 0.f, 0.f, 0.f);
        if (row < n) v = X4[row * 16 + c4];
        int c = c4 << 2;
        XsT[swidx(c + 0, r)] = v.x;
        XsT[swidx(c + 1, r)] = v.y;
        XsT[swidx(c + 2, r)] = v.z;
        XsT[swidx(c + 3, r)] = v.w;
    }
    __syncthreads();

    const int j  = tid & 63;   // output column
    const int rg = tid >> 6;   // row group (16 rows)

    unsigned long long acc2[8];
#pragma unroll
    for (int p = 0; p < 8; ++p) acc2[p] = 0ull;

#pragma unroll 8
    for (int k = 0; k < 64; ++k) {
        float wv = Ws[(k << 6) + j];
        unsigned long long wv2;
        asm("mov.b64 %0, {%1, %1};" : "=l"(wv2) : "f"(wv));

        const ulonglong2* xk = (const ulonglong2*)(XsT + (k << 6));
        int sw = (k >> 2) & 15;
        ulonglong2 a0 = xk[((rg << 2) + 0) ^ sw];   // rows +0..3 (2 packed pairs)
        ulonglong2 a1 = xk[((rg << 2) + 1) ^ sw];   // rows +4..7
        ulonglong2 a2 = xk[((rg << 2) + 2) ^ sw];   // rows +8..11
        ulonglong2 a3 = xk[((rg << 2) + 3) ^ sw];   // rows +12..15

        acc2[0] = fma2(a0.x, wv2, acc2[0]);
        acc2[1] = fma2(a0.y, wv2, acc2[1]);
        acc2[2] = fma2(a1.x, wv2, acc2[2]);
        acc2[3] = fma2(a1.y, wv2, acc2[3]);
        acc2[4] = fma2(a2.x, wv2, acc2[4]);
        acc2[5] = fma2(a2.y, wv2, acc2[5]);
        acc2[6] = fma2(a3.x, wv2, acc2[6]);
        acc2[7] = fma2(a3.y, wv2, acc2[7]);
    }

    const int rbase = row0 + (rg << 4);
    if (MODE == 0) {
#pragma unroll
        for (int p = 0; p < 8; ++p) {
            float lo, hi;
            asm("mov.b64 {%0, %1}, %2;" : "=f"(lo), "=f"(hi) : "l"(acc2[p]));
            int r0 = rbase + 2 * p;
            if (r0 < n) {
                g_xw [(size_t)r0 * 64 + j] = lo;
                g_agg[(size_t)r0 * 64 + j] = 0.f;
            }
            if (r0 + 1 < n) {
                g_xw [(size_t)(r0 + 1) * 64 + j] = hi;
                g_agg[(size_t)(r0 + 1) * 64 + j] = 0.f;
            }
        }
    } else {
        float brj = bias_r[j];
        float baj = bias_a[j];
#pragma unroll
        for (int p = 0; p < 8; ++p) {
            float lo, hi;
            asm("mov.b64 {%0, %1}, %2;" : "=f"(lo), "=f"(hi) : "l"(acc2[p]));
            int r0 = rbase + 2 * p;
            if (r0 < n) {
                float conv = g_agg[(size_t)r0 * 64 + j] + baj;
                conv = conv > 0.f ? conv : 0.f;
                float res = lo + brj;
                res = res > 0.f ? res : 0.f;
                Y[(size_t)r0 * 64 + j] = conv + res;
            }
            if (r0 + 1 < n) {
                float conv = g_agg[(size_t)(r0 + 1) * 64 + j] + baj;
                conv = conv > 0.f ? conv : 0.f;
                float res = hi + brj;
                res = res > 0.f ? res : 0.f;
                Y[(size_t)(r0 + 1) * 64 + j] = conv + res;
            }
        }
    }
}

// ============================ scatter ============================
// Vectorized 16B float atomic add (sm_90+): 4 fp32 adds per L2 atomic op.
__device__ __forceinline__ void red_add_v4(float4* addr, float4 v) {
    asm volatile("red.global.add.v4.f32 [%0], {%1, %2, %3, %4};"
                 :: "l"(addr), "f"(v.x), "f"(v.y), "f"(v.z), "f"(v.w)
                 : "memory");
}

// One thread per (edge, float4-quad): 16 threads per edge, fully coalesced
// 256B gather per edge, 16B vector red per thread.
__global__ __launch_bounds__(256)
void scatter_k(const int* __restrict__ src, const int* __restrict__ dst)
{
    unsigned gid = blockIdx.x * 256u + threadIdx.x;   // EE*16 = 19.2M exact
    unsigned e = gid >> 4;
    unsigned q = gid & 15;
    int s = __ldg(src + e);
    int d = __ldg(dst + e);
    const float4* xw4 = (const float4*)g_xw;
    float4 v = __ldg(xw4 + (size_t)s * 16 + q);
    red_add_v4(((float4*)g_agg) + (size_t)d * 16 + q, v);
}

// ============================== launch ==============================

extern "C" void kernel_launch(void* const* d_in, const int* in_sizes, int n_in,
                              void* d_out, int out_size)
{
    const float* feats = (const float*)d_in[0];
    const float* W1    = (const float*)d_in[1];
    const float* b1    = (const float*)d_in[2];
    const float* Wr1   = (const float*)d_in[3];
    const float* br1   = (const float*)d_in[4];
    const float* W2    = (const float*)d_in[5];
    const float* b2    = (const float*)d_in[6];
    const float* Wr2   = (const float*)d_in[7];
    const float* br2   = (const float*)d_in[8];
    const int*   src   = (const int*)d_in[9];
    const int*   dst   = (const int*)d_in[10];
    float*       out   = (float*)d_out;

    const int GB = (NN + 63) >> 6;            // 1563 blocks
    const int SB = (EE * 16) / 256;           // 75000 blocks

    // ---- Layer 1 ----
    gemm64_k<0, false, false><<<GB, 256>>>(feats, W1, nullptr, nullptr, nullptr, NN);
    scatter_k<<<SB, 256>>>(src, dst);
    gemm64_k<1, false, true ><<<GB, 256>>>(feats, Wr1, br1, b1, nullptr, NN);

    // ---- Layer 2 ----
    gemm64_k<0, true,  false><<<GB, 256>>>(nullptr, W2, nullptr, nullptr, nullptr, NN);
    scatter_k<<<SB, 256>>>(src, dst);
    gemm64_k<1, true,  false><<<GB, 256>>>(nullptr, Wr2, br2, b2, out, NN);
}